// round 13
// baseline (speedup 1.0000x reference)
#include <cuda_runtime.h>
#include <math.h>

#define NW   14
#define QDIM 16384
#define QBATCH 1024
#define NT   1024

typedef unsigned long long ull;

// ============ compile-time GF(2) circuit algebra ============
__host__ __device__ constexpr unsigned sig(unsigned y) { return y ^ (y >> 7); }
__host__ __device__ constexpr int cpop(unsigned x) {
    int c = 0; while (x) { c += (int)(x & 1u); x >>= 1; } return c;
}

struct PassC {
    unsigned scombo[8];   // sig(craw[2m]) per pair base
    unsigned craw[16];    // raw offsets (global, pass 0)
    unsigned sv0;         // sig(v0) pair-partner offset
    unsigned rmask[4];
    int gate[4], zflip[4], K, ngrp;
    unsigned gmask[12]; int gshift[12];
    unsigned vsv[4]; int Pmv[14];
};

__host__ __device__ constexpr unsigned hc(unsigned x, int c, int t) {
    int pc = 13 - c, pt = 13 - t;
    return x ^ (((x >> pc) & 1u) << pt);
}
__host__ __device__ constexpr unsigned Gf(unsigned x) {
    x = hc(x, 13, 0);
    for (int w = 12; w >= 0; --w) x = hc(x, w, w + 1);
    return x;
}
__host__ __device__ constexpr unsigned Gi(unsigned x) {
    for (int w = 0; w <= 12; ++w) x = hc(x, w, w + 1);
    x = hc(x, 13, 0);
    return x;
}
__host__ __device__ constexpr unsigned colV(int L, int w) {
    unsigned e = 1u << (13 - w);
    for (int i = 0; i < L; i++) e = Gf(e);
    return e;
}
__host__ __device__ constexpr unsigned rowR(int L, int w) {
    unsigned rr = 0;
    for (int j = 0; j < 14; j++) {
        unsigned e = 1u << j;
        for (int i = 0; i < L; i++) e = Gi(e);
        rr |= ((e >> (13 - w)) & 1u) << j;
    }
    return rr;
}

__host__ __device__ constexpr PassC build_pass(int pi) {
    PassC P = {};
    const int L = pi / 4, g = pi % 4;
    // layers 0,1: [4,4,3,3]; layer 2: [3,3,4,4] so the final pass is K=4
    const int gsA[4] = {0, 4, 8, 11}, gcA[4] = {4, 4, 3, 3};
    const int gsB[4] = {0, 3, 6, 10}, gcB[4] = {3, 3, 4, 4};
    const int K    = (L == 2) ? gcB[g] : gcA[g];
    const int base = (L == 2) ? gsB[g] : gsA[g];

    unsigned vs[4] = {}, rs[4] = {};
    for (int j = 0; j < K; j++) {
        vs[j] = colV(L, base + j);
        rs[j] = rowR(L, base + j);
    }
    for (int j = 0; j < 4; j++) P.vsv[j] = (j < K) ? vs[j] : 0u;

    for (int kk = 0; kk < 16; kk++) {
        unsigned cb = 0;
        if (kk < (1 << K))
            for (int j = 0; j < K; j++)
                if ((kk >> j) & 1) cb ^= vs[j];
        P.craw[kk] = cb;
    }
    for (int m = 0; m < 8; m++) P.scombo[m] = sig(P.craw[2 * m]);
    P.sv0 = sig(vs[0]);

    // Gaussian elimination, high-bit pivots
    bool ispiv[14] = {};
    unsigned red[4] = {}; int piv[4] = {};
    for (int j = 0; j < K; j++) {
        unsigned u = vs[j];
        for (int q = 0; q < j; q++)
            if ((u >> piv[q]) & 1u) u ^= red[q];
        int hb = 13;
        while (hb > 0 && !((u >> hb) & 1u)) hb--;
        piv[j] = hb; red[j] = u; ispiv[hb] = true;
    }
    const int NF = 14 - K;
    bool used[14] = {};
    for (int b = 0; b < 14; b++) used[b] = ispiv[b];

    // lane bits 0..4 -> sigma bank bits 0..4 (conflict-free scalar access)
    int Pm[14] = {};
    for (int t = 0; t < 5 && t < NF; t++) {
        int pos = -1;
        if (!used[t]) pos = t;
        else if (t + 7 < 14 && !used[t + 7]) pos = t + 7;
        if (pos < 0) { for (int b = 0; b < 14; b++) if (!used[b]) { pos = b; break; } }
        Pm[t] = pos; used[pos] = true;
    }
    for (int i = (5 < NF ? 5 : NF); i < NF; i++)
        for (int b = 0; b < 14; b++)
            if (!used[b]) { Pm[i] = b; used[b] = true; break; }
    for (int i = 0; i < 14; i++) P.Pmv[i] = (i < NF) ? Pm[i] : 0;

    unsigned freemask = 0;
    for (int i = 0; i < NF; i++) freemask |= 1u << Pm[i];
    for (int j = 0; j < 4; j++) {
        P.rmask[j] = (j < K) ? rs[j] : 0u;
        P.gate[j]  = (j < K) ? (L * 14 + base + j) : 0;
        P.zflip[j] = (j < K) ? (((rs[j] & freemask) == 0u) ? 1 : 0) : 1;
    }

    P.K = K; P.ngrp = 0;
    int i = 0;
    while (i < NF) {
        int d = Pm[i] - i;
        unsigned m = 0; int j2 = i;
        while (j2 < NF && Pm[j2] - j2 == d) { m |= 1u << j2; j2++; }
        P.gmask[P.ngrp] = m; P.gshift[P.ngrp] = d; P.ngrp++;
        i = j2;
    }
    return P;
}

struct FinC { unsigned m[14]; unsigned rmap[14]; };
__host__ __device__ constexpr FinC build_fin() {
    FinC F = {};
    PassC P = build_pass(11);
    for (int w = 0; w < 14; w++) {
        const unsigned r = rowR(3, w);
        unsigned mm = 0;
        for (int j = 0; j < 4; j++)
            if (cpop(P.vsv[j] & r) & 1) mm |= 1u << j;
        F.m[w] = mm;
        unsigned rm = 0;
        for (int i = 0; i < 10; i++)
            rm |= ((r >> P.Pmv[i]) & 1u) << i;
        F.rmap[w] = rm;
    }
    return F;
}

// ============ packed f32x2 helpers ============
__device__ __forceinline__ ull pk2(float lo, float hi) {
    ull r; asm("mov.b64 %0,{%1,%2};" : "=l"(r) : "f"(lo), "f"(hi)); return r;
}
__device__ __forceinline__ void unpk(ull v, float& lo, float& hi) {
    asm("mov.b64 {%0,%1},%2;" : "=f"(lo), "=f"(hi) : "l"(v));
}
__device__ __forceinline__ ull f2(ull a, ull b, ull c) {
    ull d; asm("fma.rn.f32x2 %0,%1,%2,%3;" : "=l"(d) : "l"(a), "l"(b), "l"(c)); return d;
}
__device__ __forceinline__ ull m2(ull a, ull b) {
    ull d; asm("mul.rn.f32x2 %0,%1,%2;" : "=l"(d) : "l"(a), "l"(b)); return d;
}

// vertical butterfly: two independent complex butterflies, zero swaps
__device__ __forceinline__ void vbfly(ull& R0, ull& I0, ull& R1, ull& I1,
                                      const ulonglong2* cv)
{
    const ulonglong2 a = cv[0], b = cv[1], c = cv[2], d = cv[3];
    const ull V0 = a.x, N1 = a.y, V2 = b.x, N3 = b.y, V1 = c.x, V3 = c.y, N2 = d.x;
    const ull r0 = R0, i0 = I0, r1 = R1, i1 = I1;
    R0 = f2(V0, r0, f2(N1, i0, f2(V2, r1, m2(N3, i1))));
    I0 = f2(V1, r0, f2(V0, i0, f2(V3, r1, m2(V2, i1))));
    R1 = f2(N2, r0, f2(N3, i0, f2(V0, r1, m2(V1, i1))));
    I1 = f2(V3, r0, f2(N2, i0, f2(N1, r1, m2(V0, i1))));
}
// horizontal butterfly: the two lanes ARE the butterfly pair
__device__ __forceinline__ void hbfly(ull& R, ull& I, const ulonglong2* ch)
{
    const ulonglong2 a = ch[0], b = ch[1], c = ch[2];
    const ull HA = a.x, HB = a.y, HC = b.x, HD = b.y, HE = c.x, HF = c.y;
    float r0, r1, i0, i1;
    unpk(R, r0, r1); unpk(I, i0, i1);
    const ull B0r = pk2(r0, r0), B0i = pk2(i0, i0);
    const ull B1r = pk2(r1, r1), B1i = pk2(i1, i1);
    R = f2(HA, B0r, f2(HB, B0i, f2(HC, B1r, m2(HD, B1i))));
    I = f2(HE, B0r, f2(HA, B0i, f2(HF, B1r, m2(HC, B1i))));
}

template<int PI>
__device__ __forceinline__ unsigned orbit_rep(int o) {
    constexpr PassC P = build_pass(PI);
    unsigned yr = 0;
    #pragma unroll
    for (int g = 0; g < P.ngrp; g++) {
        if (P.gshift[g] >= 0) yr |= ((unsigned)o & P.gmask[g]) << P.gshift[g];
        else                  yr |= ((unsigned)o & P.gmask[g]) >> (-P.gshift[g]);
    }
    return yr;
}

// ============ one fused-gate pass (uniform ELEM pairing) ============
template<int PI, bool FIRST>
__device__ __forceinline__ void do_pass(float* sRe, float* sIm,
                                        const float* __restrict__ gsrc,
                                        const ulonglong2 (*cvv)[4],
                                        const ulonglong2 (*chh)[3], int tid)
{
    constexpr PassC P = build_pass(PI);
    constexpr int K    = P.K;
    constexpr int NP   = 1 << (K - 1);
    constexpr int NORB = 1 << (NW - K);

    #pragma unroll
    for (int o = tid; o < NORB; o += NT) {
        const unsigned yr  = orbit_rep<PI>(o);
        const unsigned syr = sig(yr);

        ull R[NP], I[NP];
        if (FIRST) {
            #pragma unroll
            for (int m = 0; m < NP; m++) {
                R[m] = pk2(__ldg(gsrc + (yr ^ P.craw[2 * m])),
                           __ldg(gsrc + (yr ^ P.craw[2 * m + 1])));
                I[m] = pk2(0.0f, 0.0f);
            }
        } else {
            #pragma unroll
            for (int m = 0; m < NP; m++) {
                const unsigned f0 = syr ^ P.scombo[m], f1 = f0 ^ P.sv0;
                R[m] = pk2(sRe[f0], sRe[f1]);
                I[m] = pk2(sIm[f0], sIm[f1]);
            }
        }

        {   // gate 0: horizontal (the lane pair is the butterfly pair)
            const int flip = P.zflip[0] ? 0 : (__popc(yr & P.rmask[0]) & 1);
            const ulonglong2* ch = chh[(P.gate[0] << 1) + flip];
            #pragma unroll
            for (int m = 0; m < NP; m++) hbfly(R[m], I[m], ch);
        }
        #pragma unroll
        for (int j = 1; j < K; j++) {   // gates 1..K-1: vertical, swap-free
            const int flip = P.zflip[j] ? 0 : (__popc(yr & P.rmask[j]) & 1);
            const ulonglong2* cv = cvv[(P.gate[j] << 1) + flip];
            const int bb = 1 << (j - 1);
            #pragma unroll
            for (int m = 0; m < NP; m++)
                if (!(m & bb))
                    vbfly(R[m], I[m], R[m | bb], I[m | bb], cv);
        }

        #pragma unroll
        for (int m = 0; m < NP; m++) {
            const unsigned f0 = syr ^ P.scombo[m], f1 = f0 ^ P.sv0;
            float a, b;
            unpk(R[m], a, b); sRe[f0] = a; sRe[f1] = b;
            unpk(I[m], a, b); sIm[f0] = a; sIm[f1] = b;
        }
    }
}

// ============ final pass: gates + fused measurement ============
__device__ __forceinline__ void do_final(float* sRe, float* sIm,
                                         const ulonglong2 (*cvv)[4],
                                         const ulonglong2 (*chh)[3],
                                         int tid, float s_red[][14])
{
    constexpr PassC P = build_pass(11);
    constexpr FinC  F = build_fin();
    static_assert((1 << (NW - 4)) == NT, "final pass must be one orbit/thread");

    const unsigned yr  = orbit_rep<11>(tid);
    const unsigned syr = sig(yr);

    ull R[8], I[8];
    #pragma unroll
    for (int m = 0; m < 8; m++) {
        const unsigned f0 = syr ^ P.scombo[m], f1 = f0 ^ P.sv0;
        R[m] = pk2(sRe[f0], sRe[f1]);
        I[m] = pk2(sIm[f0], sIm[f1]);
    }
    {
        const int flip = P.zflip[0] ? 0 : (__popc(yr & P.rmask[0]) & 1);
        const ulonglong2* ch = chh[(P.gate[0] << 1) + flip];
        #pragma unroll
        for (int m = 0; m < 8; m++) hbfly(R[m], I[m], ch);
    }
    #pragma unroll
    for (int j = 1; j < 4; j++) {
        const int flip = P.zflip[j] ? 0 : (__popc(yr & P.rmask[j]) & 1);
        const ulonglong2* cv = cvv[(P.gate[j] << 1) + flip];
        const int bb = 1 << (j - 1);
        #pragma unroll
        for (int m = 0; m < 8; m++)
            if (!(m & bb))
                vbfly(R[m], I[m], R[m | bb], I[m | bb], cv);
    }

    // probabilities (element index kk = 2m + lane) + 16-point WHT
    float p[16];
    #pragma unroll
    for (int m = 0; m < 8; m++) {
        const ull pp = f2(R[m], R[m], m2(I[m], I[m]));
        unpk(pp, p[2 * m], p[2 * m + 1]);
    }
    #pragma unroll
    for (int s = 0; s < 4; s++) {
        #pragma unroll
        for (int kk = 0; kk < 16; kk++) {
            if (!((kk >> s) & 1)) {
                const int k1 = kk | (1 << s);
                const float u = p[kk], v = p[k1];
                p[kk] = u + v; p[k1] = u - v;
            }
        }
    }

    const int warp = tid >> 5, lane = tid & 31;
    #pragma unroll
    for (int w = 0; w < 14; w++) {
        float v = p[F.m[w]];
        v = (__popc((unsigned)tid & F.rmap[w]) & 1) ? -v : v;
        #pragma unroll
        for (int off = 16; off; off >>= 1)
            v += __shfl_xor_sync(0xffffffffu, v, off);
        if (lane == 0) s_red[warp][w] = v;
    }
}

// ============ kernel ============
extern __shared__ float s_dyn[];   // sRe[16384] then sIm[16384]

__global__ void __launch_bounds__(NT, 1)
qsim_kernel(const float* __restrict__ state,
            const float* __restrict__ params,
            const float* __restrict__ head_w,
            const float* __restrict__ head_b,
            float* __restrict__ out)
{
    __shared__ ulonglong2 s_v[84][4];
    __shared__ ulonglong2 s_h[84][3];
    __shared__ float s_red[NT / 32][14];
    __shared__ float s_feat[14];
    float* sRe = s_dyn;
    float* sIm = s_dyn + QDIM;

    const int tid = threadIdx.x;
    const int b   = blockIdx.x;
    const float* gsrc = state + (size_t)b * QDIM;

    // gate coefficients: U = RY(t2)*RX(t1) = [[a,b],[-b*,a*]]; flip: a->a*, b->-b*
    if (tid < 84) {
        const int g = tid >> 1, f = tid & 1;
        const float tx = params[g * 2 + 0] * 0.5f;
        const float ty = params[g * 2 + 1] * 0.5f;
        float s1, c1, s2, c2;
        sincosf(tx, &s1, &c1);
        sincosf(ty, &s2, &c2);
        float aR = c1 * c2, aI = s1 * s2;
        float bR = -s2 * c1, bI = -c2 * s1;
        if (f) { aI = -aI; bR = -bR; }
        ulonglong2 t;
        t.x = pk2(aR, aR);   t.y = pk2(-aI, -aI); s_v[tid][0] = t;
        t.x = pk2(bR, bR);   t.y = pk2(-bI, -bI); s_v[tid][1] = t;
        t.x = pk2(aI, aI);   t.y = pk2(bI, bI);   s_v[tid][2] = t;
        t.x = pk2(-bR, -bR); t.y = pk2(0.f, 0.f); s_v[tid][3] = t;
        t.x = pk2(aR, -bR);  t.y = pk2(-aI, -bI); s_h[tid][0] = t;
        t.x = pk2(bR, aR);   t.y = pk2(-bI, aI);  s_h[tid][1] = t;
        t.x = pk2(aI, bI);   t.y = pk2(bI, -aI);  s_h[tid][2] = t;
    }
    __syncthreads();

    do_pass<0,  true >(sRe, sIm, gsrc, s_v, s_h, tid); __syncthreads();
    do_pass<1,  false>(sRe, sIm, gsrc, s_v, s_h, tid); __syncthreads();
    do_pass<2,  false>(sRe, sIm, gsrc, s_v, s_h, tid); __syncthreads();
    do_pass<3,  false>(sRe, sIm, gsrc, s_v, s_h, tid); __syncthreads();
    do_pass<4,  false>(sRe, sIm, gsrc, s_v, s_h, tid); __syncthreads();
    do_pass<5,  false>(sRe, sIm, gsrc, s_v, s_h, tid); __syncthreads();
    do_pass<6,  false>(sRe, sIm, gsrc, s_v, s_h, tid); __syncthreads();
    do_pass<7,  false>(sRe, sIm, gsrc, s_v, s_h, tid); __syncthreads();
    do_pass<8,  false>(sRe, sIm, gsrc, s_v, s_h, tid); __syncthreads();
    do_pass<9,  false>(sRe, sIm, gsrc, s_v, s_h, tid); __syncthreads();
    do_pass<10, false>(sRe, sIm, gsrc, s_v, s_h, tid); __syncthreads();
    do_final(sRe, sIm, s_v, s_h, tid, s_red);
    __syncthreads();

    if (tid < 14) {
        float f = 0.0f;
        #pragma unroll
        for (int q = 0; q < NT / 32; q++) f += s_red[q][tid];
        s_feat[tid] = f * head_w[tid];
    }
    __syncthreads();
    if (tid == 0) {
        float o = head_b[0];
        #pragma unroll
        for (int w = 0; w < 14; w++) o += s_feat[w];
        out[b] = o;
    }
}

// ============ entry point ============
extern "C" void kernel_launch(void* const* d_in, const int* in_sizes, int n_in,
                              void* d_out, int out_size)
{
    (void)in_sizes; (void)n_in; (void)out_size;
    const float* state  = (const float*)d_in[0];
    const float* params = (const float*)d_in[1];
    const float* head_w = (const float*)d_in[2];
    const float* head_b = (const float*)d_in[3];
    float* out = (float*)d_out;

    const int smem = 2 * QDIM * (int)sizeof(float);   // 128 KB

    static bool attr_done = false;
    if (!attr_done) {
        cudaFuncSetAttribute(qsim_kernel,
                             cudaFuncAttributeMaxDynamicSharedMemorySize, smem);
        attr_done = true;
    }

    qsim_kernel<<<QBATCH, NT, smem>>>(state, params, head_w, head_b, out);
}

// round 14
// speedup vs baseline: 1.0558x; 1.0558x over previous
#include <cuda_runtime.h>
#include <math.h>

#define NW 14
#define QDIM 16384
#define QBATCH 1024
#define NT 1024

typedef unsigned long long ull;

// ============ compile-time GF(2) circuit algebra ============
__host__ __device__ constexpr unsigned sig(unsigned y) { return y ^ (y >> 7); }
__host__ __device__ constexpr int cpop(unsigned x) {
    int c = 0; while (x) { c += (int)(x & 1u); x >>= 1; } return c;
}

struct PassC {
    unsigned craw[16];    // raw XOR offsets
    unsigned wcombo[8];   // VERT: word offsets (sigma, bit0 cleared)
    unsigned scombo[8];   // ELEM: pair-base offsets (sigma)
    unsigned sv0;         // ELEM partner offset sig(v0)
    unsigned rmask[4];
    int gate[4], zflip[4], mv[4];
    int K, vert, ngrp, ok;
    unsigned gmask[12]; int gshift[12];
    int Pmv[14];
    unsigned vsv[4];
};

__host__ __device__ constexpr unsigned hc(unsigned x, int c, int t) {
    int pc = 13 - c, pt = 13 - t;
    return x ^ (((x >> pc) & 1u) << pt);
}
__host__ __device__ constexpr unsigned Gf(unsigned x) {
    x = hc(x, 13, 0);
    for (int w = 12; w >= 0; --w) x = hc(x, w, w + 1);
    return x;
}
__host__ __device__ constexpr unsigned Gi(unsigned x) {
    for (int w = 0; w <= 12; ++w) x = hc(x, w, w + 1);
    x = hc(x, 13, 0);
    return x;
}
__host__ __device__ constexpr unsigned colV(int L, int w) {
    unsigned e = 1u << (13 - w);
    for (int i = 0; i < L; i++) e = Gf(e);
    return e;
}
__host__ __device__ constexpr unsigned rowR(int L, int w) {
    unsigned rr = 0;
    for (int j = 0; j < 14; j++) {
        unsigned e = 1u << j;
        for (int i = 0; i < L; i++) e = Gi(e);
        rr |= ((e >> (13 - w)) & 1u) << j;
    }
    return rr;
}

__host__ __device__ constexpr PassC build_pass(int pi) {
    PassC P = {};
    const int LBY[12] = {0,0,0,0, 1,1,1,1, 2,2,2,2};
    const int KBY[12] = {4,3,3,4, 4,3,3,4, 3,3,4,4};
    const int VBY[12] = {0,1,1,0, 0,1,1,0, 1,1,0,0};
    const int WBY[12][4] = {
        {3,4,5,6}, {0,1,2,0}, {7,8,9,0}, {10,11,12,13},
        {0,1,5,6}, {2,3,4,0}, {9,10,11,0}, {7,8,12,13},
        {0,1,2,0}, {3,5,7,0}, {4,6,8,9}, {10,11,12,13}
    };
    const int L = LBY[pi], K = KBY[pi], vert = VBY[pi];

    unsigned vs[4] = {}, rs[4] = {};
    for (int j = 0; j < K; j++) {
        const int w = WBY[pi][j];
        vs[j] = colV(L, w);
        rs[j] = rowR(L, w);
        P.vsv[j] = vs[j];
    }
    for (int kk = 0; kk < 16; kk++) {
        unsigned cb = 0;
        if (kk < (1 << K))
            for (int j = 0; j < K; j++)
                if ((kk >> j) & 1) cb ^= vs[j];
        P.craw[kk] = cb;
    }
    P.sv0 = sig(vs[0]);
    for (int m = 0; m < 8; m++) {
        P.scombo[m] = sig(P.craw[2 * m]);
        P.wcombo[m] = sig(P.craw[m]) & ~1u;
    }

    // Gaussian elimination, high-bit pivots
    bool ispiv[14] = {};
    unsigned red[4] = {}; int piv[4] = {};
    for (int j = 0; j < K; j++) {
        unsigned u = vs[j];
        for (int q = 0; q < j; q++)
            if ((u >> piv[q]) & 1u) u ^= red[q];
        int hb = 13;
        while (hb > 0 && !((u >> hb) & 1u)) hb--;
        piv[j] = hb; red[j] = u; ispiv[hb] = true;
    }

    int ok = 1;
    if (vert) {
        ok &= ispiv[0] ? 0 : 1;
        for (int j = 0; j < K; j++)    // tau(vs)=0: lane order consistent
            ok &= (((vs[j] & 1u) ^ ((vs[j] >> 7) & 1u)) == 0u) ? 1 : 0;
    }

    const int ndep = 14 - K - (vert ? 1 : 0);   // = 10 for all passes
    bool used[14] = {};
    for (int b = 0; b < 14; b++) used[b] = ispiv[b];
    if (vert) used[0] = true;

    int Pm[14] = {};
    const int nlane = vert ? 4 : 5;
    for (int t = 0; t < nlane; t++) {
        int p0 = vert ? (t + 1) : t;
        int p1 = p0 + 7;
        int pos = -1;
        if (!used[p0]) pos = p0;
        else if (p1 < 14 && !used[p1]) pos = p1;
        if (pos < 0) ok = 0;
        else { Pm[t] = pos; used[pos] = true; }
    }
    for (int i = nlane; i < ndep; i++) {
        int pos = -1;
        for (int b = 0; b < 14; b++)
            if (!used[b]) { pos = b; break; }
        if (pos < 0) ok = 0;
        else { Pm[i] = pos; used[pos] = true; }
    }
    for (int i = 0; i < 14; i++) P.Pmv[i] = (i < ndep) ? Pm[i] : 0;

    unsigned freemask = 0;
    for (int i = 0; i < ndep; i++) freemask |= 1u << Pm[i];
    for (int j = 0; j < 4; j++) {
        P.rmask[j] = (j < K) ? rs[j] : 0u;
        if (j >= K) P.gate[j] = 0;
        else P.gate[j] = L * 14 + WBY[pi][j];
        P.zflip[j] = (j < K) ? (((rs[j] & freemask) == 0u) ? 1 : 0) : 1;
        P.mv[j]    = (j < K) ? (int)(rs[j] & 1u) : 0;
    }

    P.K = K; P.vert = vert; P.ok = ok; P.ngrp = 0;
    int i = 0;
    while (i < ndep) {
        int d = Pm[i] - i;
        unsigned m = 0; int j2 = i;
        while (j2 < ndep && Pm[j2] - j2 == d) { m |= 1u << j2; j2++; }
        P.gmask[P.ngrp] = m; P.gshift[P.ngrp] = d; P.ngrp++;
        i = j2;
    }
    return P;
}

struct FinC { unsigned m[14]; unsigned rmap[14]; };
__host__ __device__ constexpr FinC build_fin() {
    FinC F = {};
    PassC P = build_pass(11);
    for (int w = 0; w < 14; w++) {
        const unsigned r = rowR(3, w);
        unsigned mm = 0;
        for (int j = 0; j < 4; j++)
            if (cpop(P.vsv[j] & r) & 1) mm |= 1u << j;
        F.m[w] = mm;
        unsigned rm = 0;
        for (int i = 0; i < 10; i++)
            rm |= ((r >> P.Pmv[i]) & 1u) << i;
        F.rmap[w] = rm;
    }
    return F;
}

// ============ packed f32x2 helpers ============
__device__ __forceinline__ ull pk2(float lo, float hi) {
    ull r; asm("mov.b64 %0,{%1,%2};" : "=l"(r) : "f"(lo), "f"(hi)); return r;
}
__device__ __forceinline__ void unpk(ull v, float& lo, float& hi) {
    asm("mov.b64 {%0,%1},%2;" : "=f"(lo), "=f"(hi) : "l"(v));
}
__device__ __forceinline__ ull f2(ull a, ull b, ull c) {
    ull d; asm("fma.rn.f32x2 %0,%1,%2,%3;" : "=l"(d) : "l"(a), "l"(b), "l"(c)); return d;
}
__device__ __forceinline__ ull m2(ull a, ull b) {
    ull d; asm("mul.rn.f32x2 %0,%1,%2;" : "=l"(d) : "l"(a), "l"(b)); return d;
}

// vertical butterfly: two independent complex butterflies, zero swaps
__device__ __forceinline__ void vbfly(ull& R0, ull& I0, ull& R1, ull& I1,
                                      const ulonglong2* cv)
{
    const ulonglong2 a = cv[0], b = cv[1], c = cv[2], d = cv[3];
    const ull V0 = a.x, N1 = a.y, V2 = b.x, N3 = b.y, V1 = c.x, V3 = c.y, N2 = d.x;
    const ull r0 = R0, i0 = I0, r1 = R1, i1 = I1;
    R0 = f2(V0, r0, f2(N1, i0, f2(V2, r1, m2(N3, i1))));
    I0 = f2(V1, r0, f2(V0, i0, f2(V3, r1, m2(V2, i1))));
    R1 = f2(N2, r0, f2(N3, i0, f2(V0, r1, m2(V1, i1))));
    I1 = f2(V3, r0, f2(N2, i0, f2(N1, r1, m2(V0, i1))));
}
// horizontal butterfly: the two lanes ARE the butterfly pair
__device__ __forceinline__ void hbfly(ull& R, ull& I, const ulonglong2* ch)
{
    const ulonglong2 a = ch[0], b = ch[1], c = ch[2];
    const ull HA = a.x, HB = a.y, HC = b.x, HD = b.y, HE = c.x, HF = c.y;
    float r0, r1, i0, i1;
    unpk(R, r0, r1); unpk(I, i0, i1);
    const ull B0r = pk2(r0, r0), B0i = pk2(i0, i0);
    const ull B1r = pk2(r1, r1), B1i = pk2(i1, i1);
    R = f2(HA, B0r, f2(HB, B0i, f2(HC, B1r, m2(HD, B1i))));
    I = f2(HE, B0r, f2(HA, B0i, f2(HF, B1r, m2(HC, B1i))));
}

template<int PI>
__device__ __forceinline__ unsigned orbit_rep(int o) {
    constexpr PassC P = build_pass(PI);
    unsigned yr = 0;
    #pragma unroll
    for (int g = 0; g < P.ngrp; g++) {
        if (P.gshift[g] >= 0) yr |= ((unsigned)o & P.gmask[g]) << P.gshift[g];
        else                  yr |= ((unsigned)o & P.gmask[g]) >> (-P.gshift[g]);
    }
    return yr;
}

// ============ VERT pass: K=3, orbit-paired on state bit0, all-word LDS ============
template<int PI>
__device__ __forceinline__ void do_vert(float* sRe, float* sIm,
                                        const ulonglong2 (*vu)[4],
                                        const ulonglong2 (*vx)[4], int tid)
{
    constexpr PassC P = build_pass(PI);
    static_assert(P.vert == 1 && P.ok == 1, "VERT pass invalid");

    const unsigned yr   = orbit_rep<PI>(tid);
    const unsigned base = sig(yr) & ~1u;
    const int b7 = (int)((yr >> 7) & 1u);

    ull R[8], I[8];
    #pragma unroll
    for (int m = 0; m < 8; m++) {
        const unsigned f = base ^ P.wcombo[m];
        R[m] = *(const ull*)(sRe + f);
        I[m] = *(const ull*)(sIm + f);
    }

    #pragma unroll
    for (int j = 0; j < 3; j++) {
        const int flip = P.zflip[j] ? 0 : (__popc(yr & P.rmask[j]) & 1);
        const ulonglong2* cv = P.mv[j]
            ? vx[(P.gate[j] << 1) + (flip ^ b7)]
            : vu[(P.gate[j] << 1) + flip];
        const int bb = 1 << j;
        #pragma unroll
        for (int m = 0; m < 8; m++)
            if (!(m & bb))
                vbfly(R[m], I[m], R[m | bb], I[m | bb], cv);
    }

    #pragma unroll
    for (int m = 0; m < 8; m++) {
        const unsigned f = base ^ P.wcombo[m];
        *(ull*)(sRe + f) = R[m];
        *(ull*)(sIm + f) = I[m];
    }
}

// ============ ELEM pass: K=4, paired on gate-0 direction ============
template<int PI, bool FIRST>
__device__ __forceinline__ void do_elem(float* sRe, float* sIm,
                                        const float* __restrict__ gsrc,
                                        const ulonglong2 (*vu)[4],
                                        const ulonglong2 (*hh)[3], int tid)
{
    constexpr PassC P = build_pass(PI);
    static_assert(P.vert == 0 && P.ok == 1, "ELEM pass invalid");

    const unsigned yr  = orbit_rep<PI>(tid);
    const unsigned syr = sig(yr);

    ull R[8], I[8];
    if (FIRST) {
        #pragma unroll
        for (int m = 0; m < 8; m++) {
            R[m] = pk2(__ldg(gsrc + (yr ^ P.craw[2 * m])),
                       __ldg(gsrc + (yr ^ P.craw[2 * m + 1])));
            I[m] = pk2(0.0f, 0.0f);
        }
    } else {
        #pragma unroll
        for (int m = 0; m < 8; m++) {
            const unsigned f0 = syr ^ P.scombo[m], f1 = f0 ^ P.sv0;
            R[m] = pk2(sRe[f0], sRe[f1]);
            I[m] = pk2(sIm[f0], sIm[f1]);
        }
    }

    {   // gate 0: horizontal
        const int flip = P.zflip[0] ? 0 : (__popc(yr & P.rmask[0]) & 1);
        const ulonglong2* ch = hh[(P.gate[0] << 1) + flip];
        #pragma unroll
        for (int m = 0; m < 8; m++) hbfly(R[m], I[m], ch);
    }
    #pragma unroll
    for (int j = 1; j < 4; j++) {   // gates 1..3: vertical, swap-free
        const int flip = P.zflip[j] ? 0 : (__popc(yr & P.rmask[j]) & 1);
        const ulonglong2* cv = vu[(P.gate[j] << 1) + flip];
        const int bb = 1 << (j - 1);
        #pragma unroll
        for (int m = 0; m < 8; m++)
            if (!(m & bb))
                vbfly(R[m], I[m], R[m | bb], I[m | bb], cv);
    }

    #pragma unroll
    for (int m = 0; m < 8; m++) {
        const unsigned f0 = syr ^ P.scombo[m], f1 = f0 ^ P.sv0;
        float a, b;
        unpk(R[m], a, b); sRe[f0] = a; sRe[f1] = b;
        unpk(I[m], a, b); sIm[f0] = a; sIm[f1] = b;
    }
}

// ============ final pass (11): gates + fused measurement ============
__device__ __forceinline__ void do_final(float* sRe, float* sIm,
                                         const ulonglong2 (*vu)[4],
                                         const ulonglong2 (*hh)[3],
                                         int tid, float s_red[][14])
{
    constexpr PassC P = build_pass(11);
    constexpr FinC  F = build_fin();
    static_assert(P.vert == 0 && P.ok == 1, "final pass invalid");

    const unsigned yr  = orbit_rep<11>(tid);
    const unsigned syr = sig(yr);

    ull R[8], I[8];
    #pragma unroll
    for (int m = 0; m < 8; m++) {
        const unsigned f0 = syr ^ P.scombo[m], f1 = f0 ^ P.sv0;
        R[m] = pk2(sRe[f0], sRe[f1]);
        I[m] = pk2(sIm[f0], sIm[f1]);
    }
    {
        const int flip = P.zflip[0] ? 0 : (__popc(yr & P.rmask[0]) & 1);
        const ulonglong2* ch = hh[(P.gate[0] << 1) + flip];
        #pragma unroll
        for (int m = 0; m < 8; m++) hbfly(R[m], I[m], ch);
    }
    #pragma unroll
    for (int j = 1; j < 4; j++) {
        const int flip = P.zflip[j] ? 0 : (__popc(yr & P.rmask[j]) & 1);
        const ulonglong2* cv = vu[(P.gate[j] << 1) + flip];
        const int bb = 1 << (j - 1);
        #pragma unroll
        for (int m = 0; m < 8; m++)
            if (!(m & bb))
                vbfly(R[m], I[m], R[m | bb], I[m | bb], cv);
    }

    float p[16];
    #pragma unroll
    for (int m = 0; m < 8; m++) {
        const ull pp = f2(R[m], R[m], m2(I[m], I[m]));
        unpk(pp, p[2 * m], p[2 * m + 1]);
    }
    #pragma unroll
    for (int s = 0; s < 4; s++) {
        #pragma unroll
        for (int kk = 0; kk < 16; kk++) {
            if (!((kk >> s) & 1)) {
                const int k1 = kk | (1 << s);
                const float u = p[kk], v = p[k1];
                p[kk] = u + v; p[k1] = u - v;
            }
        }
    }

    const int warp = tid >> 5, lane = tid & 31;
    #pragma unroll
    for (int w = 0; w < 14; w++) {
        float v = p[F.m[w]];
        v = (__popc((unsigned)tid & F.rmap[w]) & 1) ? -v : v;
        #pragma unroll
        for (int off = 16; off; off >>= 1)
            v += __shfl_xor_sync(0xffffffffu, v, off);
        if (lane == 0) s_red[warp][w] = v;
    }
}

// ============ kernel ============
extern __shared__ float s_dyn[];   // sRe[16384] then sIm[16384]

__global__ void __launch_bounds__(NT, 1)
qsim_kernel(const float* __restrict__ state,
            const float* __restrict__ params,
            const float* __restrict__ head_w,
            const float* __restrict__ head_b,
            float* __restrict__ out)
{
    __shared__ ulonglong2 s_vu[84][4];   // uniform vertical (both lanes same variant)
    __shared__ ulonglong2 s_vx[84][4];   // mixed vertical (lane1 = opposite variant)
    __shared__ ulonglong2 s_h[84][3];    // horizontal
    __shared__ float s_red[NT / 32][14];
    __shared__ float s_feat[14];
    float* sRe = s_dyn;
    float* sIm = s_dyn + QDIM;

    const int tid = threadIdx.x;
    const int b   = blockIdx.x;
    const float* gsrc = state + (size_t)b * QDIM;

    // gate coefficients: U = RY(t2)*RX(t1) = [[a,b],[-b*,a*]]; flip: aI->-aI, bR->-bR
    if (tid < 84) {
        const int g = tid >> 1, q = tid & 1;
        const float tx = params[g * 2 + 0] * 0.5f;
        const float ty = params[g * 2 + 1] * 0.5f;
        float s1, c1, s2, c2;
        sincosf(tx, &s1, &c1);
        sincosf(ty, &s2, &c2);
        const float aR = c1 * c2, bI = -c2 * s1;
        float aI = s1 * s2, bR = -s2 * c1;
        if (q) { aI = -aI; bR = -bR; }
        ulonglong2 t;
        // uniform vertical
        t.x = pk2(aR, aR);   t.y = pk2(-aI, -aI); s_vu[tid][0] = t;
        t.x = pk2(bR, bR);   t.y = pk2(-bI, -bI); s_vu[tid][1] = t;
        t.x = pk2(aI, aI);   t.y = pk2(bI, bI);   s_vu[tid][2] = t;
        t.x = pk2(-bR, -bR); t.y = pk2(0.f, 0.f); s_vu[tid][3] = t;
        // mixed vertical: lane0 variant q, lane1 variant q^1 (aI1=-aI, bR1=-bR)
        t.x = pk2(aR, aR);   t.y = pk2(-aI, aI);  s_vx[tid][0] = t;
        t.x = pk2(bR, -bR);  t.y = pk2(-bI, -bI); s_vx[tid][1] = t;
        t.x = pk2(aI, -aI);  t.y = pk2(bI, bI);   s_vx[tid][2] = t;
        t.x = pk2(-bR, bR);  t.y = pk2(0.f, 0.f); s_vx[tid][3] = t;
        // horizontal
        t.x = pk2(aR, -bR);  t.y = pk2(-aI, -bI); s_h[tid][0] = t;
        t.x = pk2(bR, aR);   t.y = pk2(-bI, aI);  s_h[tid][1] = t;
        t.x = pk2(aI, bI);   t.y = pk2(bI, -aI);  s_h[tid][2] = t;
    }
    __syncthreads();

    // layer 0
    do_elem<0, true >(sRe, sIm, gsrc, s_vu, s_h, tid); __syncthreads();
    do_vert<1>(sRe, sIm, s_vu, s_vx, tid);             __syncthreads();
    do_vert<2>(sRe, sIm, s_vu, s_vx, tid);             __syncthreads();
    do_elem<3, false>(sRe, sIm, gsrc, s_vu, s_h, tid); __syncthreads();
    // layer 1
    do_elem<4, false>(sRe, sIm, gsrc, s_vu, s_h, tid); __syncthreads();
    do_vert<5>(sRe, sIm, s_vu, s_vx, tid);             __syncthreads();
    do_vert<6>(sRe, sIm, s_vu, s_vx, tid);             __syncthreads();
    do_elem<7, false>(sRe, sIm, gsrc, s_vu, s_h, tid); __syncthreads();
    // layer 2
    do_vert<8>(sRe, sIm, s_vu, s_vx, tid);             __syncthreads();
    do_vert<9>(sRe, sIm, s_vu, s_vx, tid);             __syncthreads();
    do_elem<10, false>(sRe, sIm, gsrc, s_vu, s_h, tid); __syncthreads();
    do_final(sRe, sIm, s_vu, s_h, tid, s_red);
    __syncthreads();

    if (tid < 14) {
        float f = 0.0f;
        #pragma unroll
        for (int q = 0; q < NT / 32; q++) f += s_red[q][tid];
        s_feat[tid] = f * head_w[tid];
    }
    __syncthreads();
    if (tid == 0) {
        float o = head_b[0];
        #pragma unroll
        for (int w = 0; w < 14; w++) o += s_feat[w];
        out[b] = o;
    }
}

// ============ entry point ============
extern "C" void kernel_launch(void* const* d_in, const int* in_sizes, int n_in,
                              void* d_out, int out_size)
{
    (void)in_sizes; (void)n_in; (void)out_size;
    const float* state  = (const float*)d_in[0];
    const float* params = (const float*)d_in[1];
    const float* head_w = (const float*)d_in[2];
    const float* head_b = (const float*)d_in[3];
    float* out = (float*)d_out;

    const int smem = 2 * QDIM * (int)sizeof(float);   // 128 KB

    static bool attr_done = false;
    if (!attr_done) {
        cudaFuncSetAttribute(qsim_kernel,
                             cudaFuncAttributeMaxDynamicSharedMemorySize, smem);
        attr_done = true;
    }

    qsim_kernel<<<QBATCH, NT, smem>>>(state, params, head_w, head_b, out);
}